// round 4
// baseline (speedup 1.0000x reference)
#include <cuda_runtime.h>
#include <math.h>

#define E_ 4
#define B_ 8
#define NP_ 96
#define H_ 1024
#define OUT_ 4096
#define NQ_ 144
#define FFH_ 4096

__device__ __constant__ int c_SQ[3] = {64, 48, 32};
__device__ __constant__ int c_L[3]  = {320, 304, 288};
__device__ __constant__ int c_QO[3] = {0, 64, 112};
__device__ __constant__ int c_IO[3] = {0, 256, 512};

// ---------------- scratch (device globals; no allocations allowed) ----------
__device__ float g_gates[B_ * E_];
__device__ float g_x  [NP_ * 64L * H_];
__device__ float g_xn [NP_ * 64L * H_];
__device__ float g_kv0[NP_ * 320L * H_];
__device__ float g_kvn[NP_ * 320L * H_];
__device__ float g_q  [NP_ * 64L * H_];
__device__ float g_k  [NP_ * 320L * H_];
__device__ float g_v  [NP_ * 320L * H_];
__device__ float g_h  [NP_ * 64L * FFH_];
__device__ float g_comb[B_ * (long)NQ_ * OUT_];

__device__ __forceinline__ float* bufptr(int id) {
    switch (id) {
        case 0: return g_x;  case 1: return g_xn; case 2: return g_kv0;
        case 3: return g_kvn; case 4: return g_q; case 5: return g_k;
        case 6: return g_v;  default: return g_h;
    }
}
__device__ __forceinline__ long bufstride(int id) {
    switch (id) {
        case 0: case 1: case 4: return 64L * H_;
        case 7: return 64L * FFH_;
        default: return 320L * H_;
    }
}

// ---------------- block reductions (256 threads) -----------------------------
__device__ __forceinline__ float blockReduceSum(float v, float* sbuf) {
    int t = threadIdx.x;
    for (int o = 16; o; o >>= 1) v += __shfl_down_sync(0xffffffffu, v, o);
    if ((t & 31) == 0) sbuf[t >> 5] = v;
    __syncthreads();
    if (t < 8) {
        v = sbuf[t];
        for (int o = 4; o; o >>= 1) v += __shfl_down_sync(0xffu, v, o);
        if (t == 0) sbuf[0] = v;
    }
    __syncthreads();
    float r = sbuf[0];
    __syncthreads();
    return r;
}
__device__ __forceinline__ float blockReduceMax(float v, float* sbuf) {
    int t = threadIdx.x;
    for (int o = 16; o; o >>= 1) v = fmaxf(v, __shfl_down_sync(0xffffffffu, v, o));
    if ((t & 31) == 0) sbuf[t >> 5] = v;
    __syncthreads();
    if (t < 8) {
        v = sbuf[t];
        for (int o = 4; o; o >>= 1) v = fmaxf(v, __shfl_down_sync(0xffu, v, o));
        if (t == 0) sbuf[0] = v;
    }
    __syncthreads();
    float r = sbuf[0];
    __syncthreads();
    return r;
}

// ---------------- gating -----------------------------------------------------
__global__ void gate_kernel(const float* __restrict__ img,
                            const int* __restrict__ task_ids,
                            const int* __restrict__ elem_ids,
                            const float* __restrict__ task_emb,
                            const float* __restrict__ elem_emb,
                            const float* __restrict__ glw,
                            const float* __restrict__ glb,
                            const float* __restrict__ gw,
                            const float* __restrict__ gb) {
    int b = blockIdx.x;
    int t = threadIdx.x;
    __shared__ float gi[1536];
    __shared__ float sn[1536];
    __shared__ float red[32];
    __shared__ float lg[4];

    float acc0 = 0.f, acc1 = 0.f, acc2 = 0.f, acc3 = 0.f;
    const float* ib = img + (long)b * 576 * H_;
    for (int r = 0; r < 576; r++) {
        const float* row = ib + (long)r * H_;
        acc0 += row[t];        acc1 += row[t + 256];
        acc2 += row[t + 512];  acc3 += row[t + 768];
    }
    const float inv576 = 1.f / 576.f;
    gi[t]       = acc0 * inv576;  gi[t + 256] = acc1 * inv576;
    gi[t + 512] = acc2 * inv576;  gi[t + 768] = acc3 * inv576;
    gi[1024 + t] = task_emb[task_ids[b] * 256 + t];
    gi[1280 + t] = elem_emb[elem_ids[b] * 256 + t];
    __syncthreads();

    float s1 = 0.f;
    for (int d = t; d < 1536; d += 256) s1 += gi[d];
    s1 = blockReduceSum(s1, red);
    float m = s1 / 1536.f;
    float s2 = 0.f;
    for (int d = t; d < 1536; d += 256) { float dd = gi[d] - m; s2 += dd * dd; }
    s2 = blockReduceSum(s2, red);
    float rs = rsqrtf(s2 / 1536.f + 1e-5f);
    for (int d = t; d < 1536; d += 256) sn[d] = (gi[d] - m) * rs * glw[d] + glb[d];
    __syncthreads();

    for (int e = 0; e < 4; e++) {
        float pd = 0.f;
        for (int d = t; d < 1536; d += 256) pd += sn[d] * gw[e * 1536 + d];
        pd = blockReduceSum(pd, red);
        if (t == 0) {
            float l = pd + gb[e];
            lg[e] = fminf(fmaxf(l, -15.f), 15.f);
        }
        __syncthreads();
    }
    if (t == 0) {
        float mx = fmaxf(fmaxf(lg[0], lg[1]), fmaxf(lg[2], lg[3]));
        float pe[4]; float den = 0.f;
        for (int e = 0; e < 4; e++) { pe[e] = expf(lg[e] - mx); den += pe[e]; }
        for (int e = 0; e < 4; e++) pe[e] /= den;
        int i1 = 0;
        for (int e = 1; e < 4; e++) if (pe[e] > pe[i1]) i1 = e;
        int i2 = -1;
        for (int e = 0; e < 4; e++) {
            if (e == i1) continue;
            if (i2 < 0 || pe[e] > pe[i2]) i2 = e;
        }
        float sum2 = pe[i1] + pe[i2] + 1e-9f;
        for (int e = 0; e < 4; e++) g_gates[b * 4 + e] = 0.f;
        g_gates[b * 4 + i1] = pe[i1] / sum2;
        g_gates[b * 4 + i2] = pe[i2] / sum2;
    }
}

// ---------------- build kv0 + init x -----------------------------------------
__global__ void build_kernel(const float* __restrict__ query,
                             const float* __restrict__ img,
                             const float* __restrict__ pp) {
    int p = blockIdx.y;
    int e = p / 24, r = p % 24, b = r / 3, s = r % 3;
    if (g_gates[b * 4 + e] == 0.f) return;
    int tk = blockIdx.x;
    int L = c_L[s];
    if (tk >= L) return;
    int sq = c_SQ[s];
    const float* src;
    if (tk < sq) {
        src = query + ((long)e * NQ_ + c_QO[s] + tk) * H_;
    } else {
        int j = c_IO[s] + tk - sq;
        src = (j < 576) ? img + ((long)b * 576 + j) * H_
                        : pp  + ((long)b * 192 + (j - 576)) * H_;
    }
    float* dst = g_kv0 + (long)p * 320 * H_ + (long)tk * H_;
    int t = threadIdx.x;
    float v0 = src[t], v1 = src[t + 256], v2 = src[t + 512], v3 = src[t + 768];
    dst[t] = v0; dst[t + 256] = v1; dst[t + 512] = v2; dst[t + 768] = v3;
    if (tk < sq) {
        float* xd = g_x + (long)p * 64 * H_ + (long)tk * H_;
        xd[t] = v0; xd[t + 256] = v1; xd[t + 512] = v2; xd[t + 768] = v3;
    }
}

// ---------------- row LayerNorm ----------------------------------------------
__global__ void ln_rows(int src, int dst,
                        const float* __restrict__ wbase,
                        const float* __restrict__ bbase,
                        int m_is_L, int layer) {
    int p = blockIdx.y;
    int e = p / 24, r = p % 24, b = r / 3, s = r % 3;
    if (g_gates[b * 4 + e] == 0.f) return;
    int M = m_is_L ? c_L[s] : c_SQ[s];
    int row = blockIdx.x;
    if (row >= M) return;
    const float* x = bufptr(src) + (long)p * bufstride(src) + (long)row * H_;
    float* y       = bufptr(dst) + (long)p * bufstride(dst) + (long)row * H_;
    const float* w  = wbase + (long)(e * 2 + layer) * H_;
    const float* bb = bbase + (long)(e * 2 + layer) * H_;
    __shared__ float sx[1024];
    __shared__ float red[32];
    int t = threadIdx.x;
    float s1 = 0.f;
    #pragma unroll
    for (int j = 0; j < 4; j++) { float v = x[t + j * 256]; sx[t + j * 256] = v; s1 += v; }
    s1 = blockReduceSum(s1, red);
    float m = s1 / 1024.f;
    float s2 = 0.f;
    #pragma unroll
    for (int j = 0; j < 4; j++) { float d = sx[t + j * 256] - m; s2 += d * d; }
    s2 = blockReduceSum(s2, red);
    float rs = rsqrtf(s2 / 1024.f + 1e-5f);
    #pragma unroll
    for (int j = 0; j < 4; j++) {
        int d = t + j * 256;
        y[d] = (sx[d] - m) * rs * w[d] + bb[d];
    }
}

// ---------------- generic GEMM: C[M,N] = A[M,K] @ W[N,K]^T + bias ------------
// BM=64, BN=128, BK=16, 256 threads, 4x8 microtile, double-buffered smem.
// A loader: row = tid>>2, kcol = (tid&3)*4 (one float4)    -> 32B/row coalesced
// W loader: row = tid>>1, kcol = (tid&1)*8 (two float4)    -> 64B/row coalesced
struct GArgs {
    int a_id; int c_id;
    const float* W;    long w_stride;
    const float* bias; long bias_stride;
    const float* ls;
    int N; int K;
    int m_is_L;
    int epi;     // 0 store, 1 gelu-store, 2 C += ls*(c+bias)
    int layer;
};

#define AP 68   // 68*4 = 272 B row pitch (16B multiple)

__device__ __forceinline__ void mt_compute(const float (*As)[AP], const float (*Ws)[128],
                                           int ty, int tx, float acc[4][8]) {
    #pragma unroll
    for (int kk = 0; kk < 16; kk++) {
        float4 av  = *(const float4*)&As[kk][ty * 4];
        float4 wv0 = *(const float4*)&Ws[kk][tx * 8];
        float4 wv1 = *(const float4*)&Ws[kk][tx * 8 + 4];
        float aa[4] = {av.x, av.y, av.z, av.w};
        float ww[8] = {wv0.x, wv0.y, wv0.z, wv0.w, wv1.x, wv1.y, wv1.z, wv1.w};
        #pragma unroll
        for (int i = 0; i < 4; i++)
            #pragma unroll
            for (int j = 0; j < 8; j++)
                acc[i][j] += aa[i] * ww[j];
    }
}

__device__ __forceinline__ void stage_store(float (*As)[AP], float (*Ws)[128],
                                            int arow_l, int akc, int wrow_l, int wkc,
                                            float4 ra, float4 rw0, float4 rw1) {
    As[akc + 0][arow_l] = ra.x; As[akc + 1][arow_l] = ra.y;
    As[akc + 2][arow_l] = ra.z; As[akc + 3][arow_l] = ra.w;
    Ws[wkc + 0][wrow_l] = rw0.x; Ws[wkc + 1][wrow_l] = rw0.y;
    Ws[wkc + 2][wrow_l] = rw0.z; Ws[wkc + 3][wrow_l] = rw0.w;
    Ws[wkc + 4][wrow_l] = rw1.x; Ws[wkc + 5][wrow_l] = rw1.y;
    Ws[wkc + 6][wrow_l] = rw1.z; Ws[wkc + 7][wrow_l] = rw1.w;
}

__global__ void __launch_bounds__(256) gemm_k(GArgs g) {
    int p = blockIdx.z;
    int e = p / 24, r = p % 24, b = r / 3, s = r % 3;
    if (g_gates[b * 4 + e] == 0.f) return;
    int M = g.m_is_L ? c_L[s] : c_SQ[s];
    int m0 = blockIdx.x * 64;
    if (m0 >= M) return;
    int n0 = blockIdx.y * 128;

    const float* A    = bufptr(g.a_id) + (long)p * bufstride(g.a_id);
    const float* W    = g.W    + (long)(e * 2 + g.layer) * g.w_stride;
    const float* bias = g.bias + (long)(e * 2 + g.layer) * g.bias_stride;
    float* C          = bufptr(g.c_id) + (long)p * bufstride(g.c_id);

    __shared__ float As[2][16][AP];
    __shared__ float Ws[2][16][128];

    int tid = threadIdx.x;
    int ty = tid >> 4, tx = tid & 15;

    int arow_l = tid >> 2, akc = (tid & 3) << 2;
    int wrow_l = tid >> 1, wkc = (tid & 1) << 3;

    bool aval = (m0 + arow_l) < M;
    const float* aptr = A + (long)(m0 + arow_l) * g.K + akc;
    const float* wptr = W + (long)(n0 + wrow_l) * g.K + wkc;

    float acc[4][8];
    #pragma unroll
    for (int i = 0; i < 4; i++)
        #pragma unroll
        for (int j = 0; j < 8; j++) acc[i][j] = 0.f;

    int nc = g.K >> 4;
    float4 ra = make_float4(0.f, 0.f, 0.f, 0.f), rw0, rw1;
    if (aval) ra = *(const float4*)(aptr);
    rw0 = *(const float4*)(wptr);
    rw1 = *(const float4*)(wptr + 4);
    stage_store(As[0], Ws[0], arow_l, akc, wrow_l, wkc, ra, rw0, rw1);
    __syncthreads();

    for (int c = 0; c < nc; c++) {
        int cur = c & 1;
        bool nx = (c + 1 < nc);
        if (nx) {
            long off = (long)(c + 1) << 4;
            ra = make_float4(0.f, 0.f, 0.f, 0.f);
            if (aval) ra = *(const float4*)(aptr + off);
            rw0 = *(const float4*)(wptr + off);
            rw1 = *(const float4*)(wptr + off + 4);
        }
        mt_compute(As[cur], Ws[cur], ty, tx, acc);
        if (nx) stage_store(As[cur ^ 1], Ws[cur ^ 1], arow_l, akc, wrow_l, wkc, ra, rw0, rw1);
        __syncthreads();
    }

    const float* lsp = (g.epi == 2) ? (g.ls + (long)(e * 2 + g.layer) * H_) : nullptr;
    #pragma unroll
    for (int i = 0; i < 4; i++) {
        int m = m0 + ty * 4 + i;
        if (m >= M) continue;
        #pragma unroll
        for (int j = 0; j < 8; j++) {
            int n = n0 + tx * 8 + j;
            float v = acc[i][j] + bias[n];
            long idx = (long)m * g.N + n;
            if (g.epi == 0) {
                C[idx] = v;
            } else if (g.epi == 1) {
                C[idx] = v * 0.5f * (1.f + erff(v * 0.70710678118654752f));
            } else {
                C[idx] += lsp[n] * v;
            }
        }
    }
}

// ---------------- attention (per problem, head, q-row) -----------------------
__global__ void attn_kernel() {
    int p = blockIdx.z;
    int e = p / 24, r = p % 24, b = r / 3, s = r % 3;
    if (g_gates[b * 4 + e] == 0.f) return;
    int sq = c_SQ[s];
    int row = blockIdx.x;
    if (row >= sq) return;
    int L = c_L[s];
    int h = blockIdx.y;
    int t = threadIdx.x;

    __shared__ float sc[320];
    __shared__ float qv[64];
    __shared__ float red[32];
    __shared__ float cbuf[4][64];

    const float* Q = g_q + (long)p * 64 * H_ + (long)row * H_ + h * 64;
    const float* K = g_k + (long)p * 320 * H_ + h * 64;
    const float* V = g_v + (long)p * 320 * H_ + h * 64;

    if (t < 64) qv[t] = Q[t];
    __syncthreads();

    for (int k = t; k < L; k += 256) {
        const float* kr = K + (long)k * H_;
        float d = 0.f;
        #pragma unroll
        for (int dd = 0; dd < 64; dd++) d += qv[dd] * kr[dd];
        sc[k] = d * 0.125f;
    }
    __syncthreads();

    float mx = -1e30f;
    for (int k = t; k < L; k += 256) mx = fmaxf(mx, sc[k]);
    mx = blockReduceMax(mx, red);
    float sum = 0.f;
    for (int k = t; k < L; k += 256) { float ev = expf(sc[k] - mx); sc[k] = ev; sum += ev; }
    sum = blockReduceSum(sum, red);
    float inv = 1.f / sum;

    int d = t & 63, ch = t >> 6;
    float acc = 0.f;
    for (int k = ch; k < L; k += 4) acc += sc[k] * V[(long)k * H_ + d];
    cbuf[ch][d] = acc;
    __syncthreads();
    if (t < 64) {
        float o = (cbuf[0][t] + cbuf[1][t] + cbuf[2][t] + cbuf[3][t]) * inv;
        g_xn[(long)p * 64 * H_ + (long)row * H_ + h * 64 + t] = o;
    }
}

// ---------------- expert-weighted output projection --------------------------
__global__ void __launch_bounds__(256) out_gemm(const float* __restrict__ outp_w,
                                                const float* __restrict__ outp_b) {
    int b = blockIdx.z;
    int m0 = blockIdx.x * 64;
    int n0 = blockIdx.y * 128;

    __shared__ float As[2][16][AP];
    __shared__ float Ws[2][16][128];

    int tid = threadIdx.x;
    int ty = tid >> 4, tx = tid & 15;
    int arow_l = tid >> 2, akc = (tid & 3) << 2;
    int wrow_l = tid >> 1, wkc = (tid & 1) << 3;

    int qg = m0 + arow_l;
    bool aval = qg < NQ_;
    int s = 0, lr = 0;
    if (aval) {
        s = (qg < 64) ? 0 : ((qg < 112) ? 1 : 2);
        lr = qg - c_QO[s];
    }

    float tot[4][8];
    #pragma unroll
    for (int i = 0; i < 4; i++)
        #pragma unroll
        for (int j = 0; j < 8; j++) tot[i][j] = 0.f;

    for (int e = 0; e < 4; e++) {
        float gt = g_gates[b * 4 + e];
        if (gt == 0.f) continue;
        const float* aptr = g_x + ((long)(e * 24 + b * 3 + s) * 64 + lr) * H_ + akc;
        const float* wptr = outp_w + (long)e * OUT_ * H_ + (long)(n0 + wrow_l) * H_ + wkc;

        float acc[4][8];
        #pragma unroll
        for (int i = 0; i < 4; i++)
            #pragma unroll
            for (int j = 0; j < 8; j++) acc[i][j] = 0.f;

        float4 ra = make_float4(0.f, 0.f, 0.f, 0.f), rw0, rw1;
        if (aval) ra = *(const float4*)(aptr);
        rw0 = *(const float4*)(wptr);
        rw1 = *(const float4*)(wptr + 4);
        __syncthreads();  // previous expert's reads done before refill
        stage_store(As[0], Ws[0], arow_l, akc, wrow_l, wkc, ra, rw0, rw1);
        __syncthreads();

        const int nc = H_ >> 4;
        for (int c = 0; c < nc; c++) {
            int cur = c & 1;
            bool nx = (c + 1 < nc);
            if (nx) {
                long off = (long)(c + 1) << 4;
                ra = make_float4(0.f, 0.f, 0.f, 0.f);
                if (aval) ra = *(const float4*)(aptr + off);
                rw0 = *(const float4*)(wptr + off);
                rw1 = *(const float4*)(wptr + off + 4);
            }
            mt_compute(As[cur], Ws[cur], ty, tx, acc);
            if (nx) stage_store(As[cur ^ 1], Ws[cur ^ 1], arow_l, akc, wrow_l, wkc, ra, rw0, rw1);
            __syncthreads();
        }

        const float* bias = outp_b + (long)e * OUT_;
        #pragma unroll
        for (int i = 0; i < 4; i++)
            #pragma unroll
            for (int j = 0; j < 8; j++)
                tot[i][j] += gt * (acc[i][j] + bias[n0 + tx * 8 + j]);
    }

    #pragma unroll
    for (int i = 0; i < 4; i++) {
        int m = m0 + ty * 4 + i;
        if (m >= NQ_) continue;
        #pragma unroll
        for (int j = 0; j < 8; j++) {
            int n = n0 + tx * 8 + j;
            g_comb[((long)b * NQ_ + m) * OUT_ + n] = tot[i][j];
        }
    }
}

// ---------------- final RMS + scaling ----------------------------------------
__global__ void rms_kernel(const float* __restrict__ final_w,
                           const float* __restrict__ out_gain,
                           float* __restrict__ out) {
    int q = blockIdx.x, b = blockIdx.y;
    int t = threadIdx.x;
    const float* c = g_comb + ((long)b * NQ_ + q) * OUT_;
    float s2 = 0.f;
    for (int o = t; o < OUT_; o += 256) { float v = c[o]; s2 += v * v; }
    __shared__ float red[32];
    s2 = blockReduceSum(s2, red);
    float rs = rsqrtf(s2 / (float)OUT_ + 1e-6f);
    float* orow = out + ((long)b * NQ_ + q) * OUT_;
    for (int o = t; o < OUT_; o += 256) orow[o] = c[o] * rs * final_w[o] * out_gain[o];
}

// ---------------- host driver ------------------------------------------------
extern "C" void kernel_launch(void* const* d_in, const int* in_sizes, int n_in,
                              void* d_out, int out_size) {
    const float* image_embs = (const float*)d_in[0];
    const float* phys       = (const float*)d_in[1];
    const int*   task_ids   = (const int*)d_in[2];
    const int*   elem_ids   = (const int*)d_in[3];
    const float* query      = (const float*)d_in[4];
    const float* ln1_w      = (const float*)d_in[5];
    const float* ln1_b      = (const float*)d_in[6];
    const float* ln1kv_w    = (const float*)d_in[7];
    const float* ln1kv_b    = (const float*)d_in[8];
    const float* attn_in_w  = (const float*)d_in[9];
    const float* attn_in_b  = (const float*)d_in[10];
    const float* attn_out_w = (const float*)d_in[11];
    const float* attn_out_b = (const float*)d_in[12];
    const float* ls1        = (const float*)d_in[13];
    const float* ls2        = (const float*)d_in[14];
    const float* ln2_w      = (const float*)d_in[15];
    const float* ln2_b      = (const float*)d_in[16];
    const float* fc_w       = (const float*)d_in[17];
    const float* fc_b       = (const float*)d_in[18];
    const float* proj_w     = (const float*)d_in[19];
    const float* proj_b     = (const float*)d_in[20];
    const float* outp_w     = (const float*)d_in[21];
    const float* outp_b     = (const float*)d_in[22];
    const float* task_emb   = (const float*)d_in[23];
    const float* elem_emb   = (const float*)d_in[24];
    const float* gate_ln_w  = (const float*)d_in[25];
    const float* gate_ln_b  = (const float*)d_in[26];
    const float* gate_w     = (const float*)d_in[27];
    const float* gate_b     = (const float*)d_in[28];
    const float* output_gain= (const float*)d_in[29];
    const float* final_w    = (const float*)d_in[30];
    (void)in_sizes; (void)n_in; (void)out_size;

    gate_kernel<<<B_, 256>>>(image_embs, task_ids, elem_ids, task_emb, elem_emb,
                             gate_ln_w, gate_ln_b, gate_w, gate_b);
    build_kernel<<<dim3(320, NP_), 256>>>(query, image_embs, phys);

    for (int l = 0; l < 2; l++) {
        ln_rows<<<dim3(320, NP_), 256>>>(2, 3, ln1kv_w, ln1kv_b, 1, l);
        ln_rows<<<dim3(64, NP_), 256>>>(0, 1, ln1_w, ln1_b, 0, l);

        GArgs gq = {};
        gq.a_id = 1; gq.c_id = 4;
        gq.W = attn_in_w; gq.w_stride = 3072L * 1024;
        gq.bias = attn_in_b; gq.bias_stride = 3072;
        gq.ls = nullptr; gq.N = 1024; gq.K = 1024;
        gq.m_is_L = 0; gq.epi = 0; gq.layer = l;
        gemm_k<<<dim3(1, 8, NP_), 256>>>(gq);

        GArgs gk = gq;
        gk.a_id = 3; gk.c_id = 5;
        gk.W = attn_in_w + 1024L * 1024; gk.bias = attn_in_b + 1024;
        gk.m_is_L = 1;
        gemm_k<<<dim3(5, 8, NP_), 256>>>(gk);

        GArgs gv = gk;
        gv.c_id = 6;
        gv.W = attn_in_w + 2048L * 1024; gv.bias = attn_in_b + 2048;
        gemm_k<<<dim3(5, 8, NP_), 256>>>(gv);

        attn_kernel<<<dim3(64, 16, NP_), 256>>>();

        GArgs go = {};
        go.a_id = 1; go.c_id = 0;
        go.W = attn_out_w; go.w_stride = 1024L * 1024;
        go.bias = attn_out_b; go.bias_stride = 1024;
        go.ls = ls1; go.N = 1024; go.K = 1024;
        go.m_is_L = 0; go.epi = 2; go.layer = l;
        gemm_k<<<dim3(1, 8, NP_), 256>>>(go);

        ln_rows<<<dim3(64, NP_), 256>>>(0, 1, ln2_w, ln2_b, 0, l);

        GArgs gf = {};
        gf.a_id = 1; gf.c_id = 7;
        gf.W = fc_w; gf.w_stride = 4096L * 1024;
        gf.bias = fc_b; gf.bias_stride = 4096;
        gf.ls = nullptr; gf.N = 4096; gf.K = 1024;
        gf.m_is_L = 0; gf.epi = 1; gf.layer = l;
        gemm_k<<<dim3(1, 32, NP_), 256>>>(gf);

        GArgs gp = {};
        gp.a_id = 7; gp.c_id = 0;
        gp.W = proj_w; gp.w_stride = 1024L * 4096;
        gp.bias = proj_b; gp.bias_stride = 1024;
        gp.ls = ls2; gp.N = 1024; gp.K = 4096;
        gp.m_is_L = 0; gp.epi = 2; gp.layer = l;
        gemm_k<<<dim3(1, 8, NP_), 256>>>(gp);
    }

    out_gemm<<<dim3(3, 32, B_), 256>>>(outp_w, outp_b);
    rms_kernel<<<dim3(NQ_, B_), 256>>>(final_w, output_gain, (float*)d_out);
}

// round 5
// speedup vs baseline: 1.5988x; 1.5988x over previous
#include <cuda_runtime.h>
#include <cuda_bf16.h>
#include <math.h>
#include <stdint.h>

#define E_ 4
#define B_ 8
#define NP_ 96
#define H_ 1024
#define OUT_ 4096
#define NQ_ 144
#define FFH_ 4096

__device__ __constant__ int c_SQ[3] = {64, 48, 32};
__device__ __constant__ int c_L[3]  = {320, 304, 288};
__device__ __constant__ int c_QO[3] = {0, 64, 112};
__device__ __constant__ int c_IO[3] = {0, 256, 512};

// ---------------- scratch (device globals; no allocations allowed) ----------
__device__ float g_gates[B_ * E_];
__device__ float g_x  [NP_ * 64L * H_];
__device__ float g_xn [NP_ * 64L * H_];
__device__ float g_kv0[NP_ * 320L * H_];
__device__ float g_kvn[NP_ * 320L * H_];
__device__ float g_q  [NP_ * 64L * H_];
__device__ float g_k  [NP_ * 320L * H_];
__device__ float g_v  [NP_ * 320L * H_];
__device__ float g_h  [NP_ * 64L * FFH_];
__device__ float g_comb[B_ * (long)NQ_ * OUT_];

// split-bf16 weight storage (hi/lo)
#define OFF_ATTNIN  0L
#define SZ_ATTNIN   25165824L     // 4*2*3072*1024
#define OFF_ATTNOUT 25165824L
#define SZ_ATTNOUT  8388608L      // 4*2*1024*1024
#define OFF_FC      33554432L
#define SZ_FC       33554432L     // 4*2*4096*1024
#define OFF_PROJ    67108864L
#define SZ_PROJ     33554432L
#define OFF_OUTP    100663296L
#define SZ_OUTP     16777216L     // 4*4096*1024
#define W_TOTAL     117440512L

__device__ __nv_bfloat16 g_wh[W_TOTAL];
__device__ __nv_bfloat16 g_wl[W_TOTAL];

__device__ __forceinline__ float* bufptr(int id) {
    switch (id) {
        case 0: return g_x;  case 1: return g_xn; case 2: return g_kv0;
        case 3: return g_kvn; case 4: return g_q; case 5: return g_k;
        case 6: return g_v;  default: return g_h;
    }
}
__device__ __forceinline__ long bufstride(int id) {
    switch (id) {
        case 0: case 1: case 4: return 64L * H_;
        case 7: return 64L * FFH_;
        default: return 320L * H_;
    }
}

// ---------------- weight splitting ------------------------------------------
__global__ void split_w(const float* __restrict__ src, long off, long n) {
    long i = (long)blockIdx.x * blockDim.x + threadIdx.x;
    long stride = (long)gridDim.x * blockDim.x;
    for (; i < n; i += stride) {
        float x = src[i];
        __nv_bfloat16 h = __float2bfloat16(x);
        g_wh[off + i] = h;
        g_wl[off + i] = __float2bfloat16(x - __bfloat162float(h));
    }
}

// ---------------- block reductions (256 threads) -----------------------------
__device__ __forceinline__ float blockReduceSum(float v, float* sbuf) {
    int t = threadIdx.x;
    for (int o = 16; o; o >>= 1) v += __shfl_down_sync(0xffffffffu, v, o);
    if ((t & 31) == 0) sbuf[t >> 5] = v;
    __syncthreads();
    if (t < 8) {
        v = sbuf[t];
        for (int o = 4; o; o >>= 1) v += __shfl_down_sync(0xffu, v, o);
        if (t == 0) sbuf[0] = v;
    }
    __syncthreads();
    float r = sbuf[0];
    __syncthreads();
    return r;
}
__device__ __forceinline__ float blockReduceMax(float v, float* sbuf) {
    int t = threadIdx.x;
    for (int o = 16; o; o >>= 1) v = fmaxf(v, __shfl_down_sync(0xffffffffu, v, o));
    if ((t & 31) == 0) sbuf[t >> 5] = v;
    __syncthreads();
    if (t < 8) {
        v = sbuf[t];
        for (int o = 4; o; o >>= 1) v = fmaxf(v, __shfl_down_sync(0xffu, v, o));
        if (t == 0) sbuf[0] = v;
    }
    __syncthreads();
    float r = sbuf[0];
    __syncthreads();
    return r;
}

// ---------------- gating -----------------------------------------------------
__global__ void gate_kernel(const float* __restrict__ img,
                            const int* __restrict__ task_ids,
                            const int* __restrict__ elem_ids,
                            const float* __restrict__ task_emb,
                            const float* __restrict__ elem_emb,
                            const float* __restrict__ glw,
                            const float* __restrict__ glb,
                            const float* __restrict__ gw,
                            const float* __restrict__ gb) {
    int b = blockIdx.x;
    int t = threadIdx.x;
    __shared__ float gi[1536];
    __shared__ float sn[1536];
    __shared__ float red[32];
    __shared__ float lg[4];

    float acc0 = 0.f, acc1 = 0.f, acc2 = 0.f, acc3 = 0.f;
    const float* ib = img + (long)b * 576 * H_;
    for (int r = 0; r < 576; r++) {
        const float* row = ib + (long)r * H_;
        acc0 += row[t];        acc1 += row[t + 256];
        acc2 += row[t + 512];  acc3 += row[t + 768];
    }
    const float inv576 = 1.f / 576.f;
    gi[t]       = acc0 * inv576;  gi[t + 256] = acc1 * inv576;
    gi[t + 512] = acc2 * inv576;  gi[t + 768] = acc3 * inv576;
    gi[1024 + t] = task_emb[task_ids[b] * 256 + t];
    gi[1280 + t] = elem_emb[elem_ids[b] * 256 + t];
    __syncthreads();

    float s1 = 0.f;
    for (int d = t; d < 1536; d += 256) s1 += gi[d];
    s1 = blockReduceSum(s1, red);
    float m = s1 / 1536.f;
    float s2 = 0.f;
    for (int d = t; d < 1536; d += 256) { float dd = gi[d] - m; s2 += dd * dd; }
    s2 = blockReduceSum(s2, red);
    float rs = rsqrtf(s2 / 1536.f + 1e-5f);
    for (int d = t; d < 1536; d += 256) sn[d] = (gi[d] - m) * rs * glw[d] + glb[d];
    __syncthreads();

    for (int e = 0; e < 4; e++) {
        float pd = 0.f;
        for (int d = t; d < 1536; d += 256) pd += sn[d] * gw[e * 1536 + d];
        pd = blockReduceSum(pd, red);
        if (t == 0) {
            float l = pd + gb[e];
            lg[e] = fminf(fmaxf(l, -15.f), 15.f);
        }
        __syncthreads();
    }
    if (t == 0) {
        float mx = fmaxf(fmaxf(lg[0], lg[1]), fmaxf(lg[2], lg[3]));
        float pe[4]; float den = 0.f;
        for (int e = 0; e < 4; e++) { pe[e] = expf(lg[e] - mx); den += pe[e]; }
        for (int e = 0; e < 4; e++) pe[e] /= den;
        int i1 = 0;
        for (int e = 1; e < 4; e++) if (pe[e] > pe[i1]) i1 = e;
        int i2 = -1;
        for (int e = 0; e < 4; e++) {
            if (e == i1) continue;
            if (i2 < 0 || pe[e] > pe[i2]) i2 = e;
        }
        float sum2 = pe[i1] + pe[i2] + 1e-9f;
        for (int e = 0; e < 4; e++) g_gates[b * 4 + e] = 0.f;
        g_gates[b * 4 + i1] = pe[i1] / sum2;
        g_gates[b * 4 + i2] = pe[i2] / sum2;
    }
}

// ---------------- build kv0 + init x -----------------------------------------
__global__ void build_kernel(const float* __restrict__ query,
                             const float* __restrict__ img,
                             const float* __restrict__ pp) {
    int p = blockIdx.y;
    int e = p / 24, r = p % 24, b = r / 3, s = r % 3;
    if (g_gates[b * 4 + e] == 0.f) return;
    int tk = blockIdx.x;
    int L = c_L[s];
    if (tk >= L) return;
    int sq = c_SQ[s];
    const float* src;
    if (tk < sq) {
        src = query + ((long)e * NQ_ + c_QO[s] + tk) * H_;
    } else {
        int j = c_IO[s] + tk - sq;
        src = (j < 576) ? img + ((long)b * 576 + j) * H_
                        : pp  + ((long)b * 192 + (j - 576)) * H_;
    }
    float* dst = g_kv0 + (long)p * 320 * H_ + (long)tk * H_;
    int t = threadIdx.x;
    float v0 = src[t], v1 = src[t + 256], v2 = src[t + 512], v3 = src[t + 768];
    dst[t] = v0; dst[t + 256] = v1; dst[t + 512] = v2; dst[t + 768] = v3;
    if (tk < sq) {
        float* xd = g_x + (long)p * 64 * H_ + (long)tk * H_;
        xd[t] = v0; xd[t + 256] = v1; xd[t + 512] = v2; xd[t + 768] = v3;
    }
}

// ---------------- row LayerNorm ----------------------------------------------
__global__ void ln_rows(int src, int dst,
                        const float* __restrict__ wbase,
                        const float* __restrict__ bbase,
                        int m_is_L, int layer) {
    int p = blockIdx.y;
    int e = p / 24, r = p % 24, b = r / 3, s = r % 3;
    if (g_gates[b * 4 + e] == 0.f) return;
    int M = m_is_L ? c_L[s] : c_SQ[s];
    int row = blockIdx.x;
    if (row >= M) return;
    const float* x = bufptr(src) + (long)p * bufstride(src) + (long)row * H_;
    float* y       = bufptr(dst) + (long)p * bufstride(dst) + (long)row * H_;
    const float* w  = wbase + (long)(e * 2 + layer) * H_;
    const float* bb = bbase + (long)(e * 2 + layer) * H_;
    __shared__ float sx[1024];
    __shared__ float red[32];
    int t = threadIdx.x;
    float s1 = 0.f;
    #pragma unroll
    for (int j = 0; j < 4; j++) { float v = x[t + j * 256]; sx[t + j * 256] = v; s1 += v; }
    s1 = blockReduceSum(s1, red);
    float m = s1 / 1024.f;
    float s2 = 0.f;
    #pragma unroll
    for (int j = 0; j < 4; j++) { float d = sx[t + j * 256] - m; s2 += d * d; }
    s2 = blockReduceSum(s2, red);
    float rs = rsqrtf(s2 / 1024.f + 1e-5f);
    #pragma unroll
    for (int j = 0; j < 4; j++) {
        int d = t + j * 256;
        y[d] = (sx[d] - m) * rs * w[d] + bb[d];
    }
}

// ---------------- tensor-core GEMM (split bf16, 3-product) -------------------
// C[M,N] = A[M,K] @ W[N,K]^T + bias.  Block tile 64x64, 128 threads (4 warps,
// each 32x32), BK=32.  A fp32->split in loader; W pre-split in g_wh/g_wl.
#define SPITCH 40   // bf16 elems per smem row (80B, conflict-free phases)

struct GArgs {
    int a_id; int c_id;
    long wh_off; long w_stride;
    const float* bias; long bias_stride;
    const float* ls;
    int N; int K;
    int m_is_L;
    int epi;     // 0 store, 1 gelu-store, 2 C += ls*(c+bias)
    int layer;
};

__device__ __forceinline__ void mma_bf16(float* d, const uint32_t* a, const uint32_t* b) {
    asm volatile(
        "mma.sync.aligned.m16n8k16.row.col.f32.bf16.bf16.f32 "
        "{%0,%1,%2,%3}, {%4,%5,%6,%7}, {%8,%9}, {%0,%1,%2,%3};\n"
        : "+f"(d[0]), "+f"(d[1]), "+f"(d[2]), "+f"(d[3])
        : "r"(a[0]), "r"(a[1]), "r"(a[2]), "r"(a[3]), "r"(b[0]), "r"(b[1]));
}

__device__ __forceinline__ void pack_store(__nv_bfloat16* sh, __nv_bfloat16* sl,
                                           int base, float4 f) {
    __nv_bfloat162 h0 = __floats2bfloat162_rn(f.x, f.y);
    __nv_bfloat162 h1 = __floats2bfloat162_rn(f.z, f.w);
    float2 g0 = __bfloat1622float2(h0), g1 = __bfloat1622float2(h1);
    __nv_bfloat162 l0 = __floats2bfloat162_rn(f.x - g0.x, f.y - g0.y);
    __nv_bfloat162 l1 = __floats2bfloat162_rn(f.z - g1.x, f.w - g1.y);
    *(__nv_bfloat162*)(sh + base)     = h0;
    *(__nv_bfloat162*)(sh + base + 2) = h1;
    *(__nv_bfloat162*)(sl + base)     = l0;
    *(__nv_bfloat162*)(sl + base + 2) = l1;
}

__device__ __forceinline__ uint32_t ld2(const __nv_bfloat16* p) {
    return *(const uint32_t*)p;
}

__global__ void __launch_bounds__(128) gemm_k(GArgs g) {
    int p = blockIdx.z;
    int e = p / 24, r = p % 24, b = r / 3, s = r % 3;
    if (g_gates[b * 4 + e] == 0.f) return;
    int M = g.m_is_L ? c_L[s] : c_SQ[s];
    int m0 = blockIdx.x * 64;
    if (m0 >= M) return;
    int n0 = blockIdx.y * 64;

    const float* A = bufptr(g.a_id) + (long)p * bufstride(g.a_id);
    const __nv_bfloat16* Wh = g_wh + g.wh_off + (long)(e * 2 + g.layer) * g.w_stride;
    const __nv_bfloat16* Wl = g_wl + g.wh_off + (long)(e * 2 + g.layer) * g.w_stride;
    const float* bias = g.bias + (long)(e * 2 + g.layer) * g.bias_stride;
    float* C = bufptr(g.c_id) + (long)p * bufstride(g.c_id);

    __shared__ __nv_bfloat16 sAh[64 * SPITCH], sAl[64 * SPITCH];
    __shared__ __nv_bfloat16 sWh[64 * SPITCH], sWl[64 * SPITCH];

    int tid = threadIdx.x;
    // loader: each thread handles one row-half: row = tid>>1, 16 k elems
    int lrow = tid >> 1, lkb = (tid & 1) << 4;
    bool aval = (m0 + lrow) < M;
    const float* aptr = A + (long)(m0 + lrow) * g.K + lkb;
    const __nv_bfloat16* whp = Wh + (long)(n0 + lrow) * g.K + lkb;
    const __nv_bfloat16* wlp = Wl + (long)(n0 + lrow) * g.K + lkb;

    // compute mapping
    int lane = tid & 31, w = tid >> 5;
    int gq_ = lane >> 2, qq = lane & 3;
    int wm = w >> 1, wn = w & 1;
    int abase = wm * 32;
    int wbase = wn * 32;

    float acc[2][4][4];
    #pragma unroll
    for (int i = 0; i < 2; i++)
        #pragma unroll
        for (int j = 0; j < 4; j++)
            #pragma unroll
            for (int k = 0; k < 4; k++) acc[i][j][k] = 0.f;

    int nc = g.K >> 5;
    float4 fa0, fa1, fa2, fa3;
    uint4 vh0, vh1, vl0, vl1;

    // prefetch chunk 0
    fa0 = fa1 = fa2 = fa3 = make_float4(0.f, 0.f, 0.f, 0.f);
    if (aval) {
        fa0 = *(const float4*)(aptr);      fa1 = *(const float4*)(aptr + 4);
        fa2 = *(const float4*)(aptr + 8);  fa3 = *(const float4*)(aptr + 12);
    }
    vh0 = *(const uint4*)(whp);  vh1 = *(const uint4*)(whp + 8);
    vl0 = *(const uint4*)(wlp);  vl1 = *(const uint4*)(wlp + 8);

    for (int c = 0; c < nc; c++) {
        int sb = lrow * SPITCH + lkb;
        pack_store(sAh, sAl, sb,      fa0);
        pack_store(sAh, sAl, sb + 4,  fa1);
        pack_store(sAh, sAl, sb + 8,  fa2);
        pack_store(sAh, sAl, sb + 12, fa3);
        *(uint4*)&sWh[sb]     = vh0;  *(uint4*)&sWh[sb + 8] = vh1;
        *(uint4*)&sWl[sb]     = vl0;  *(uint4*)&sWl[sb + 8] = vl1;
        __syncthreads();

        if (c + 1 < nc) {
            long off = (long)(c + 1) << 5;
            fa0 = fa1 = fa2 = fa3 = make_float4(0.f, 0.f, 0.f, 0.f);
            if (aval) {
                fa0 = *(const float4*)(aptr + off);      fa1 = *(const float4*)(aptr + off + 4);
                fa2 = *(const float4*)(aptr + off + 8);  fa3 = *(const float4*)(aptr + off + 12);
            }
            vh0 = *(const uint4*)(whp + off);  vh1 = *(const uint4*)(whp + off + 8);
            vl0 = *(const uint4*)(wlp + off);  vl1 = *(const uint4*)(wlp + off + 8);
        }

        #pragma unroll
        for (int ks = 0; ks < 32; ks += 16) {
            int cb = ks + qq * 2;
            uint32_t Ah[2][4], Al[2][4], Bh[4][2], Bl[4][2];
            #pragma unroll
            for (int mf = 0; mf < 2; mf++) {
                int rr = (abase + mf * 16 + gq_) * SPITCH;
                Ah[mf][0] = ld2(&sAh[rr + cb]);
                Ah[mf][1] = ld2(&sAh[rr + 8 * SPITCH + cb]);
                Ah[mf][2] = ld2(&sAh[rr + cb + 8]);
                Ah[mf][3] = ld2(&sAh[rr + 8 * SPITCH + cb + 8]);
                Al[mf][0] = ld2(&sAl[rr + cb]);
                Al[mf][1] = ld2(&sAl[rr + 8 * SPITCH + cb]);
                Al[mf][2] = ld2(&sAl[rr + cb + 8]);
                Al[mf][3] = ld2(&sAl[rr + 8 * SPITCH + cb + 8]);
            }
            #pragma unroll
            for (int nf = 0; nf < 4; nf++) {
                int rr = (wbase + nf * 8 + gq_) * SPITCH;
                Bh[nf][0] = ld2(&sWh[rr + cb]);
                Bh[nf][1] = ld2(&sWh[rr + cb + 8]);
                Bl[nf][0] = ld2(&sWl[rr + cb]);
                Bl[nf][1] = ld2(&sWl[rr + cb + 8]);
            }
            #pragma unroll
            for (int mf = 0; mf < 2; mf++)
                #pragma unroll
                for (int nf = 0; nf < 4; nf++) {
                    mma_bf16(acc[mf][nf], Ah[mf], Bh[nf]);
                    mma_bf16(acc[mf][nf], Ah[mf], Bl[nf]);
                    mma_bf16(acc[mf][nf], Al[mf], Bh[nf]);
                }
        }
        __syncthreads();
    }

    const float* lsp = (g.epi == 2) ? (g.ls + (long)(e * 2 + g.layer) * H_) : nullptr;
    #pragma unroll
    for (int mf = 0; mf < 2; mf++) {
        #pragma unroll
        for (int half = 0; half < 2; half++) {
            int m = m0 + abase + mf * 16 + gq_ + half * 8;
            if (m >= M) continue;
            #pragma unroll
            for (int nf = 0; nf < 4; nf++) {
                int n = n0 + wbase + nf * 8 + qq * 2;
                float v0 = acc[mf][nf][half * 2 + 0] + bias[n];
                float v1 = acc[mf][nf][half * 2 + 1] + bias[n + 1];
                long idx = (long)m * g.N + n;
                if (g.epi == 0) {
                    C[idx] = v0; C[idx + 1] = v1;
                } else if (g.epi == 1) {
                    C[idx]     = v0 * 0.5f * (1.f + erff(v0 * 0.70710678118654752f));
                    C[idx + 1] = v1 * 0.5f * (1.f + erff(v1 * 0.70710678118654752f));
                } else {
                    C[idx]     += lsp[n] * v0;
                    C[idx + 1] += lsp[n + 1] * v1;
                }
            }
        }
    }
}

// ---------------- attention (per problem, head, q-row) -----------------------
__global__ void attn_kernel() {
    int p = blockIdx.z;
    int e = p / 24, r = p % 24, b = r / 3, s = r % 3;
    if (g_gates[b * 4 + e] == 0.f) return;
    int sq = c_SQ[s];
    int row = blockIdx.x;
    if (row >= sq) return;
    int L = c_L[s];
    int h = blockIdx.y;
    int t = threadIdx.x;

    __shared__ float sc[320];
    __shared__ float qv[64];
    __shared__ float red[32];
    __shared__ float cbuf[4][64];

    const float* Q = g_q + (long)p * 64 * H_ + (long)row * H_ + h * 64;
    const float* K = g_k + (long)p * 320 * H_ + h * 64;
    const float* V = g_v + (long)p * 320 * H_ + h * 64;

    if (t < 64) qv[t] = Q[t];
    __syncthreads();

    for (int k = t; k < L; k += 256) {
        const float* kr = K + (long)k * H_;
        float d = 0.f;
        #pragma unroll
        for (int dd = 0; dd < 64; dd++) d += qv[dd] * kr[dd];
        sc[k] = d * 0.125f;
    }
    __syncthreads();

    float mx = -1e30f;
    for (int k = t; k < L; k += 256) mx = fmaxf(mx, sc[k]);
    mx = blockReduceMax(mx, red);
    float sum = 0.f;
    for (int k = t; k < L; k += 256) { float ev = expf(sc[k] - mx); sc[k] = ev; sum += ev; }
    sum = blockReduceSum(sum, red);
    float inv = 1.f / sum;

    int d = t & 63, ch = t >> 6;
    float acc = 0.f;
    for (int k = ch; k < L; k += 4) acc += sc[k] * V[(long)k * H_ + d];
    cbuf[ch][d] = acc;
    __syncthreads();
    if (t < 64) {
        float o = (cbuf[0][t] + cbuf[1][t] + cbuf[2][t] + cbuf[3][t]) * inv;
        g_xn[(long)p * 64 * H_ + (long)row * H_ + h * 64 + t] = o;
    }
}

// ---------------- expert-weighted output projection (tensor core) ------------
__global__ void __launch_bounds__(128) out_gemm(const float* __restrict__ outp_b) {
    int b = blockIdx.z;
    int m0 = blockIdx.x * 64;
    int n0 = blockIdx.y * 64;

    __shared__ __nv_bfloat16 sAh[64 * SPITCH], sAl[64 * SPITCH];
    __shared__ __nv_bfloat16 sWh[64 * SPITCH], sWl[64 * SPITCH];

    int tid = threadIdx.x;
    int lrow = tid >> 1, lkb = (tid & 1) << 4;
    int lane = tid & 31, w = tid >> 5;
    int gq_ = lane >> 2, qq = lane & 3;
    int wm = w >> 1, wn = w & 1;
    int abase = wm * 32, wbase = wn * 32;

    int qg = m0 + lrow;
    bool aval = qg < NQ_;
    int s = 0, lr = 0;
    if (aval) {
        s = (qg < 64) ? 0 : ((qg < 112) ? 1 : 2);
        lr = qg - c_QO[s];
    }

    float tot[2][4][4];
    #pragma unroll
    for (int i = 0; i < 2; i++)
        #pragma unroll
        for (int j = 0; j < 4; j++)
            #pragma unroll
            for (int k = 0; k < 4; k++) tot[i][j][k] = 0.f;

    for (int e = 0; e < 4; e++) {
        float gt = g_gates[b * 4 + e];
        if (gt == 0.f) continue;
        const float* aptr = g_x + ((long)(e * 24 + b * 3 + s) * 64 + lr) * H_ + lkb;
        long wb_off = OFF_OUTP + (long)e * OUT_ * H_ + (long)(n0 + lrow) * H_ + lkb;
        const __nv_bfloat16* whp = g_wh + wb_off;
        const __nv_bfloat16* wlp = g_wl + wb_off;

        float acc[2][4][4];
        #pragma unroll
        for (int i = 0; i < 2; i++)
            #pragma unroll
            for (int j = 0; j < 4; j++)
                #pragma unroll
                for (int k = 0; k < 4; k++) acc[i][j][k] = 0.f;

        float4 fa0, fa1, fa2, fa3;
        uint4 vh0, vh1, vl0, vl1;
        fa0 = fa1 = fa2 = fa3 = make_float4(0.f, 0.f, 0.f, 0.f);
        if (aval) {
            fa0 = *(const float4*)(aptr);      fa1 = *(const float4*)(aptr + 4);
            fa2 = *(const float4*)(aptr + 8);  fa3 = *(const float4*)(aptr + 12);
        }
        vh0 = *(const uint4*)(whp);  vh1 = *(const uint4*)(whp + 8);
        vl0 = *(const uint4*)(wlp);  vl1 = *(const uint4*)(wlp + 8);

        const int nc = H_ >> 5;
        for (int c = 0; c < nc; c++) {
            int sb = lrow * SPITCH + lkb;
            pack_store(sAh, sAl, sb,      fa0);
            pack_store(sAh, sAl, sb + 4,  fa1);
            pack_store(sAh, sAl, sb + 8,  fa2);
            pack_store(sAh, sAl, sb + 12, fa3);
            *(uint4*)&sWh[sb]     = vh0;  *(uint4*)&sWh[sb + 8] = vh1;
            *(uint4*)&sWl[sb]     = vl0;  *(uint4*)&sWl[sb + 8] = vl1;
            __syncthreads();

            if (c + 1 < nc) {
                long off = (long)(c + 1) << 5;
                fa0 = fa1 = fa2 = fa3 = make_float4(0.f, 0.f, 0.f, 0.f);
                if (aval) {
                    fa0 = *(const float4*)(aptr + off);      fa1 = *(const float4*)(aptr + off + 4);
                    fa2 = *(const float4*)(aptr + off + 8);  fa3 = *(const float4*)(aptr + off + 12);
                }
                vh0 = *(const uint4*)(whp + off);  vh1 = *(const uint4*)(whp + off + 8);
                vl0 = *(const uint4*)(wlp + off);  vl1 = *(const uint4*)(wlp + off + 8);
            }

            #pragma unroll
            for (int ks = 0; ks < 32; ks += 16) {
                int cb = ks + qq * 2;
                uint32_t Ah[2][4], Al[2][4], Bh[4][2], Bl[4][2];
                #pragma unroll
                for (int mf = 0; mf < 2; mf++) {
                    int rr = (abase + mf * 16 + gq_) * SPITCH;
                    Ah[mf][0] = ld2(&sAh[rr + cb]);
                    Ah[mf][1] = ld2(&sAh[rr + 8 * SPITCH + cb]);
                    Ah[mf][2] = ld2(&sAh[rr + cb + 8]);
                    Ah[mf][3] = ld2(&sAh[rr + 8 * SPITCH + cb + 8]);
                    Al[mf][0] = ld2(&sAl[rr + cb]);
                    Al[mf][1] = ld2(&sAl[rr + 8 * SPITCH + cb]);
                    Al[mf][2] = ld2(&sAl[rr + cb + 8]);
                    Al[mf][3] = ld2(&sAl[rr + 8 * SPITCH + cb + 8]);
                }
                #pragma unroll
                for (int nf = 0; nf < 4; nf++) {
                    int rr = (wbase + nf * 8 + gq_) * SPITCH;
                    Bh[nf][0] = ld2(&sWh[rr + cb]);
                    Bh[nf][1] = ld2(&sWh[rr + cb + 8]);
                    Bl[nf][0] = ld2(&sWl[rr + cb]);
                    Bl[nf][1] = ld2(&sWl[rr + cb + 8]);
                }
                #pragma unroll
                for (int mf = 0; mf < 2; mf++)
                    #pragma unroll
                    for (int nf = 0; nf < 4; nf++) {
                        mma_bf16(acc[mf][nf], Ah[mf], Bh[nf]);
                        mma_bf16(acc[mf][nf], Ah[mf], Bl[nf]);
                        mma_bf16(acc[mf][nf], Al[mf], Bh[nf]);
                    }
            }
            __syncthreads();
        }

        const float* bias = outp_b + (long)e * OUT_;
        #pragma unroll
        for (int mf = 0; mf < 2; mf++)
            #pragma unroll
            for (int nf = 0; nf < 4; nf++) {
                int n = n0 + wbase + nf * 8 + qq * 2;
                tot[mf][nf][0] += gt * (acc[mf][nf][0] + bias[n]);
                tot[mf][nf][1] += gt * (acc[mf][nf][1] + bias[n + 1]);
                tot[mf][nf][2] += gt * (acc[mf][nf][2] + bias[n]);
                tot[mf][nf][3] += gt * (acc[mf][nf][3] + bias[n + 1]);
            }
    }

    #pragma unroll
    for (int mf = 0; mf < 2; mf++) {
        #pragma unroll
        for (int half = 0; half < 2; half++) {
            int m = m0 + abase + mf * 16 + gq_ + half * 8;
            if (m >= NQ_) continue;
            #pragma unroll
            for (int nf = 0; nf < 4; nf++) {
                int n = n0 + wbase + nf * 8 + qq * 2;
                g_comb[((long)b * NQ_ + m) * OUT_ + n]     = tot[mf][nf][half * 2 + 0];
                g_comb[((long)b * NQ_ + m) * OUT_ + n + 1] = tot[mf][nf][half * 2 + 1];
            }
        }
    }
}

// ---------------- final RMS + scaling ----------------------------------------
__global__ void rms_kernel(const float* __restrict__ final_w,
                           const float* __restrict__ out_gain,
                           float* __restrict__ out) {
    int q = blockIdx.x, b = blockIdx.y;
    int t = threadIdx.x;
    const float* c = g_comb + ((long)b * NQ_ + q) * OUT_;
    float s2 = 0.f;
    for (int o = t; o < OUT_; o += 256) { float v = c[o]; s2 += v * v; }
    __shared__ float red[32];
    s2 = blockReduceSum(s2, red);
    float rs = rsqrtf(s2 / (float)OUT_ + 1e-6f);
    float* orow = out + ((long)b * NQ_ + q) * OUT_;
    for (int o = t; o < OUT_; o += 256) orow[o] = c[o] * rs * final_w[o] * out_gain[o];
}

// ---------------- host driver ------------------------------------------------
extern "C" void kernel_launch(void* const* d_in, const int* in_sizes, int n_in,
                              void* d_out, int out_size) {
    const float* image_embs = (const float*)d_in[0];
    const float* phys       = (const float*)d_in[1];
    const int*   task_ids   = (const int*)d_in[2];
    const int*   elem_ids   = (const int*)d_in[3];
    const float* query      = (const float*)d_in[4];
    const float* ln1_w      = (const float*)d_in[5];
    const float* ln1_b      = (const float*)d_in[6];
    const float* ln1kv_w    = (const float*)d_in[7];
    const float* ln1kv_b    = (const float*)d_in[8];
    const float* attn_in_w  = (const float*)d_in[9];
    const float* attn_in_b  = (const float*)d_in[10];
    const float* attn_out_w = (const float*)d_in[11];
    const float* attn_out_b = (const float*)d_in[12];
    const float* ls1        = (const float*)d_in[13];
    const float* ls2        = (const float*)d_in[14];
    const float* ln2_w      = (const float*)d_in[15];
    const float* ln2_b      = (const float*)d_in[16];
    const float* fc_w       = (const float*)d_in[17];
    const float* fc_b       = (const float*)d_in[18];
    const float* proj_w     = (const float*)d_in[19];
    const float* proj_b     = (const float*)d_in[20];
    const float* outp_w     = (const float*)d_in[21];
    const float* outp_b     = (const float*)d_in[22];
    const float* task_emb   = (const float*)d_in[23];
    const float* elem_emb   = (const float*)d_in[24];
    const float* gate_ln_w  = (const float*)d_in[25];
    const float* gate_ln_b  = (const float*)d_in[26];
    const float* gate_w     = (const float*)d_in[27];
    const float* gate_b     = (const float*)d_in[28];
    const float* output_gain= (const float*)d_in[29];
    const float* final_w    = (const float*)d_in[30];
    (void)in_sizes; (void)n_in; (void)out_size;

    // split weights into bf16 hi/lo
    split_w<<<4096, 256>>>(attn_in_w,  OFF_ATTNIN,  SZ_ATTNIN);
    split_w<<<2048, 256>>>(attn_out_w, OFF_ATTNOUT, SZ_ATTNOUT);
    split_w<<<4096, 256>>>(fc_w,       OFF_FC,      SZ_FC);
    split_w<<<4096, 256>>>(proj_w,     OFF_PROJ,    SZ_PROJ);
    split_w<<<4096, 256>>>(outp_w,     OFF_OUTP,    SZ_OUTP);

    gate_kernel<<<B_, 256>>>(image_embs, task_ids, elem_ids, task_emb, elem_emb,
                             gate_ln_w, gate_ln_b, gate_w, gate_b);
    build_kernel<<<dim3(320, NP_), 256>>>(query, image_embs, phys);

    for (int l = 0; l < 2; l++) {
        ln_rows<<<dim3(320, NP_), 256>>>(2, 3, ln1kv_w, ln1kv_b, 1, l);
        ln_rows<<<dim3(64, NP_), 256>>>(0, 1, ln1_w, ln1_b, 0, l);

        GArgs gq = {};
        gq.a_id = 1; gq.c_id = 4;
        gq.wh_off = OFF_ATTNIN; gq.w_stride = 3072L * 1024;
        gq.bias = attn_in_b; gq.bias_stride = 3072;
        gq.ls = nullptr; gq.N = 1024; gq.K = 1024;
        gq.m_is_L = 0; gq.epi = 0; gq.layer = l;
        gemm_k<<<dim3(1, 16, NP_), 128>>>(gq);

        GArgs gk = gq;
        gk.a_id = 3; gk.c_id = 5;
        gk.wh_off = OFF_ATTNIN + 1024L * 1024; gk.bias = attn_in_b + 1024;
        gk.m_is_L = 1;
        gemm_k<<<dim3(5, 16, NP_), 128>>>(gk);

        GArgs gv = gk;
        gv.c_id = 6;
        gv.wh_off = OFF_ATTNIN + 2048L * 1024; gv.bias = attn_in_b + 2048;
        gemm_k<<<dim3(5, 16, NP_), 128>>>(gv);

        attn_kernel<<<dim3(64, 16, NP_), 256>>>();

        GArgs go = {};
        go.a_id = 1; go.c_id = 0;
        go.wh_off = OFF_ATTNOUT; go.w_stride = 1024L * 1024;
        go.bias = attn_out_b; go.bias_stride = 1024;
        go.ls = ls1; go.N = 1024; go.K = 1024;
        go.m_is_L = 0; go.epi = 2; go.layer = l;
        gemm_k<<<dim3(1, 16, NP_), 128>>>(go);

        ln_rows<<<dim3(64, NP_), 256>>>(0, 1, ln2_w, ln2_b, 0, l);

        GArgs gf = {};
        gf.a_id = 1; gf.c_id = 7;
        gf.wh_off = OFF_FC; gf.w_stride = 4096L * 1024;
        gf.bias = fc_b; gf.bias_stride = 4096;
        gf.ls = nullptr; gf.N = 4096; gf.K = 1024;
        gf.m_is_L = 0; gf.epi = 1; gf.layer = l;
        gemm_k<<<dim3(1, 64, NP_), 128>>>(gf);

        GArgs gp = {};
        gp.a_id = 7; gp.c_id = 0;
        gp.wh_off = OFF_PROJ; gp.w_stride = 1024L * 4096;
        gp.bias = proj_b; gp.bias_stride = 1024;
        gp.ls = ls2; gp.N = 1024; gp.K = 4096;
        gp.m_is_L = 0; gp.epi = 2; gp.layer = l;
        gemm_k<<<dim3(1, 16, NP_), 128>>>(gp);
    }

    out_gemm<<<dim3(3, 64, B_), 128>>>(outp_b);
    rms_kernel<<<dim3(NQ_, B_), 256>>>(final_w, output_gain, (float*)d_out);
}

// round 6
// speedup vs baseline: 1.6959x; 1.0608x over previous
#include <cuda_runtime.h>
#include <cuda_bf16.h>
#include <math.h>
#include <stdint.h>

#define E_ 4
#define B_ 8
#define NP_ 96
#define H_ 1024
#define OUT_ 4096
#define NQ_ 144
#define FFH_ 4096

__device__ __constant__ int c_SQ[3] = {64, 48, 32};
__device__ __constant__ int c_L[3]  = {320, 304, 288};
__device__ __constant__ int c_QO[3] = {0, 64, 112};
__device__ __constant__ int c_IO[3] = {0, 256, 512};

// ---------------- scratch (device globals; no allocations allowed) ----------
__device__ float g_gates[B_ * E_];
__device__ float g_x  [NP_ * 64L * H_];
__device__ float g_xn [NP_ * 64L * H_];
__device__ float g_kv0[NP_ * 320L * H_];
__device__ float g_kvn[NP_ * 320L * H_];
__device__ float g_q  [NP_ * 64L * H_];
__device__ float g_k  [NP_ * 320L * H_];
__device__ float g_v  [NP_ * 320L * H_];
__device__ float g_h  [NP_ * 64L * FFH_];
__device__ float g_comb[B_ * (long)NQ_ * OUT_];

// split-bf16 weight storage (hi/lo)
#define OFF_ATTNIN  0L
#define SZ_ATTNIN   25165824L
#define OFF_ATTNOUT 25165824L
#define SZ_ATTNOUT  8388608L
#define OFF_FC      33554432L
#define SZ_FC       33554432L
#define OFF_PROJ    67108864L
#define SZ_PROJ     33554432L
#define OFF_OUTP    100663296L
#define SZ_OUTP     16777216L
#define W_TOTAL     117440512L

__device__ __nv_bfloat16 g_wh[W_TOTAL];
__device__ __nv_bfloat16 g_wl[W_TOTAL];

__device__ __forceinline__ float* bufptr(int id) {
    switch (id) {
        case 0: return g_x;  case 1: return g_xn; case 2: return g_kv0;
        case 3: return g_kvn; case 4: return g_q; case 5: return g_k;
        case 6: return g_v;  default: return g_h;
    }
}
__device__ __forceinline__ long bufstride(int id) {
    switch (id) {
        case 0: case 1: case 4: return 64L * H_;
        case 7: return 64L * FFH_;
        default: return 320L * H_;
    }
}

// ---------------- weight splitting ------------------------------------------
__global__ void split_w(const float* __restrict__ src, long off, long n) {
    long i = (long)blockIdx.x * blockDim.x + threadIdx.x;
    long stride = (long)gridDim.x * blockDim.x;
    for (; i < n; i += stride) {
        float x = src[i];
        __nv_bfloat16 h = __float2bfloat16(x);
        g_wh[off + i] = h;
        g_wl[off + i] = __float2bfloat16(x - __bfloat162float(h));
    }
}

// ---------------- block reductions (256 threads) -----------------------------
__device__ __forceinline__ float blockReduceSum(float v, float* sbuf) {
    int t = threadIdx.x;
    for (int o = 16; o; o >>= 1) v += __shfl_down_sync(0xffffffffu, v, o);
    if ((t & 31) == 0) sbuf[t >> 5] = v;
    __syncthreads();
    if (t < 8) {
        v = sbuf[t];
        for (int o = 4; o; o >>= 1) v += __shfl_down_sync(0xffu, v, o);
        if (t == 0) sbuf[0] = v;
    }
    __syncthreads();
    float r = sbuf[0];
    __syncthreads();
    return r;
}
__device__ __forceinline__ float blockReduceMax(float v, float* sbuf) {
    int t = threadIdx.x;
    for (int o = 16; o; o >>= 1) v = fmaxf(v, __shfl_down_sync(0xffffffffu, v, o));
    if ((t & 31) == 0) sbuf[t >> 5] = v;
    __syncthreads();
    if (t < 8) {
        v = sbuf[t];
        for (int o = 4; o; o >>= 1) v = fmaxf(v, __shfl_down_sync(0xffu, v, o));
        if (t == 0) sbuf[0] = v;
    }
    __syncthreads();
    float r = sbuf[0];
    __syncthreads();
    return r;
}

// ---------------- gating -----------------------------------------------------
__global__ void gate_kernel(const float* __restrict__ img,
                            const int* __restrict__ task_ids,
                            const int* __restrict__ elem_ids,
                            const float* __restrict__ task_emb,
                            const float* __restrict__ elem_emb,
                            const float* __restrict__ glw,
                            const float* __restrict__ glb,
                            const float* __restrict__ gw,
                            const float* __restrict__ gb) {
    int b = blockIdx.x;
    int t = threadIdx.x;
    __shared__ float gi[1536];
    __shared__ float sn[1536];
    __shared__ float red[32];
    __shared__ float lg[4];

    float acc0 = 0.f, acc1 = 0.f, acc2 = 0.f, acc3 = 0.f;
    const float* ib = img + (long)b * 576 * H_;
    for (int r = 0; r < 576; r++) {
        const float* row = ib + (long)r * H_;
        acc0 += row[t];        acc1 += row[t + 256];
        acc2 += row[t + 512];  acc3 += row[t + 768];
    }
    const float inv576 = 1.f / 576.f;
    gi[t]       = acc0 * inv576;  gi[t + 256] = acc1 * inv576;
    gi[t + 512] = acc2 * inv576;  gi[t + 768] = acc3 * inv576;
    gi[1024 + t] = task_emb[task_ids[b] * 256 + t];
    gi[1280 + t] = elem_emb[elem_ids[b] * 256 + t];
    __syncthreads();

    float s1 = 0.f;
    for (int d = t; d < 1536; d += 256) s1 += gi[d];
    s1 = blockReduceSum(s1, red);
    float m = s1 / 1536.f;
    float s2 = 0.f;
    for (int d = t; d < 1536; d += 256) { float dd = gi[d] - m; s2 += dd * dd; }
    s2 = blockReduceSum(s2, red);
    float rs = rsqrtf(s2 / 1536.f + 1e-5f);
    for (int d = t; d < 1536; d += 256) sn[d] = (gi[d] - m) * rs * glw[d] + glb[d];
    __syncthreads();

    for (int e = 0; e < 4; e++) {
        float pd = 0.f;
        for (int d = t; d < 1536; d += 256) pd += sn[d] * gw[e * 1536 + d];
        pd = blockReduceSum(pd, red);
        if (t == 0) {
            float l = pd + gb[e];
            lg[e] = fminf(fmaxf(l, -15.f), 15.f);
        }
        __syncthreads();
    }
    if (t == 0) {
        float mx = fmaxf(fmaxf(lg[0], lg[1]), fmaxf(lg[2], lg[3]));
        float pe[4]; float den = 0.f;
        for (int e = 0; e < 4; e++) { pe[e] = expf(lg[e] - mx); den += pe[e]; }
        for (int e = 0; e < 4; e++) pe[e] /= den;
        int i1 = 0;
        for (int e = 1; e < 4; e++) if (pe[e] > pe[i1]) i1 = e;
        int i2 = -1;
        for (int e = 0; e < 4; e++) {
            if (e == i1) continue;
            if (i2 < 0 || pe[e] > pe[i2]) i2 = e;
        }
        float sum2 = pe[i1] + pe[i2] + 1e-9f;
        for (int e = 0; e < 4; e++) g_gates[b * 4 + e] = 0.f;
        g_gates[b * 4 + i1] = pe[i1] / sum2;
        g_gates[b * 4 + i2] = pe[i2] / sum2;
    }
}

// ---------------- build kv0 + init x -----------------------------------------
__global__ void build_kernel(const float* __restrict__ query,
                             const float* __restrict__ img,
                             const float* __restrict__ pp) {
    int p = blockIdx.y;
    int e = p / 24, r = p % 24, b = r / 3, s = r % 3;
    if (g_gates[b * 4 + e] == 0.f) return;
    int tk = blockIdx.x;
    int L = c_L[s];
    if (tk >= L) return;
    int sq = c_SQ[s];
    const float* src;
    if (tk < sq) {
        src = query + ((long)e * NQ_ + c_QO[s] + tk) * H_;
    } else {
        int j = c_IO[s] + tk - sq;
        src = (j < 576) ? img + ((long)b * 576 + j) * H_
                        : pp  + ((long)b * 192 + (j - 576)) * H_;
    }
    float* dst = g_kv0 + (long)p * 320 * H_ + (long)tk * H_;
    int t = threadIdx.x;
    float v0 = src[t], v1 = src[t + 256], v2 = src[t + 512], v3 = src[t + 768];
    dst[t] = v0; dst[t + 256] = v1; dst[t + 512] = v2; dst[t + 768] = v3;
    if (tk < sq) {
        float* xd = g_x + (long)p * 64 * H_ + (long)tk * H_;
        xd[t] = v0; xd[t + 256] = v1; xd[t + 512] = v2; xd[t + 768] = v3;
    }
}

// ---------------- row LayerNorm ----------------------------------------------
__global__ void ln_rows(int src, int dst,
                        const float* __restrict__ wbase,
                        const float* __restrict__ bbase,
                        int m_is_L, int layer) {
    int p = blockIdx.y;
    int e = p / 24, r = p % 24, b = r / 3, s = r % 3;
    if (g_gates[b * 4 + e] == 0.f) return;
    int M = m_is_L ? c_L[s] : c_SQ[s];
    int row = blockIdx.x;
    if (row >= M) return;
    const float* x = bufptr(src) + (long)p * bufstride(src) + (long)row * H_;
    float* y       = bufptr(dst) + (long)p * bufstride(dst) + (long)row * H_;
    const float* w  = wbase + (long)(e * 2 + layer) * H_;
    const float* bb = bbase + (long)(e * 2 + layer) * H_;
    __shared__ float sx[1024];
    __shared__ float red[32];
    int t = threadIdx.x;
    float s1 = 0.f;
    #pragma unroll
    for (int j = 0; j < 4; j++) { float v = x[t + j * 256]; sx[t + j * 256] = v; s1 += v; }
    s1 = blockReduceSum(s1, red);
    float m = s1 / 1024.f;
    float s2 = 0.f;
    #pragma unroll
    for (int j = 0; j < 4; j++) { float d = sx[t + j * 256] - m; s2 += d * d; }
    s2 = blockReduceSum(s2, red);
    float rs = rsqrtf(s2 / 1024.f + 1e-5f);
    #pragma unroll
    for (int j = 0; j < 4; j++) {
        int d = t + j * 256;
        y[d] = (sx[d] - m) * rs * w[d] + bb[d];
    }
}

// ---------------- tensor-core GEMM v2 ---------------------------------------
// C[M,N] = A[M,K] @ W[N,K]^T + bias.  Split bf16 (hi/lo), 3-product mma.
// Block tile 64x128, BK=32, 256 threads = 8 warps (2 x 4), warp tile 32x32.
// 2-stage dynamic smem, ldmatrix fragment loads.
#define SPITCH 40   // bf16 per smem row (80B pitch; 8 consecutive rows hit 8 phases)

// dynamic smem layout per stage (bytes):
//   A_hi: 64*SPITCH*2  = 5120
//   A_lo: +5120
//   W_hi: +10240 (128*SPITCH*2 = 10240)
//   W_lo: +20480
#define STG_BYTES 30720
#define SMEM_TOTAL (2 * STG_BYTES)

struct GArgs {
    int a_id; int c_id;
    long wh_off; long w_stride;
    const float* bias; long bias_stride;
    const float* ls;
    int N; int K;
    int m_is_L;
    int epi;     // 0 store, 1 gelu-store, 2 C += ls*(c+bias)
    int layer;
};

__device__ __forceinline__ void mma_bf16(float* d, const uint32_t* a, const uint32_t* b) {
    asm volatile(
        "mma.sync.aligned.m16n8k16.row.col.f32.bf16.bf16.f32 "
        "{%0,%1,%2,%3}, {%4,%5,%6,%7}, {%8,%9}, {%0,%1,%2,%3};\n"
        : "+f"(d[0]), "+f"(d[1]), "+f"(d[2]), "+f"(d[3])
        : "r"(a[0]), "r"(a[1]), "r"(a[2]), "r"(a[3]), "r"(b[0]), "r"(b[1]));
}

__device__ __forceinline__ void ldsm4(uint32_t& r0, uint32_t& r1, uint32_t& r2, uint32_t& r3,
                                      uint32_t addr) {
    asm volatile("ldmatrix.sync.aligned.m8n8.x4.shared.b16 {%0,%1,%2,%3}, [%4];"
                 : "=r"(r0), "=r"(r1), "=r"(r2), "=r"(r3) : "r"(addr));
}

__device__ __forceinline__ void pack_store(__nv_bfloat16* sh, __nv_bfloat16* sl,
                                           int base, float4 f) {
    __nv_bfloat162 h0 = __floats2bfloat162_rn(f.x, f.y);
    __nv_bfloat162 h1 = __floats2bfloat162_rn(f.z, f.w);
    float2 g0 = __bfloat1622float2(h0), g1 = __bfloat1622float2(h1);
    __nv_bfloat162 l0 = __floats2bfloat162_rn(f.x - g0.x, f.y - g0.y);
    __nv_bfloat162 l1 = __floats2bfloat162_rn(f.z - g1.x, f.w - g1.y);
    *(__nv_bfloat162*)(sh + base)     = h0;
    *(__nv_bfloat162*)(sh + base + 2) = h1;
    *(__nv_bfloat162*)(sl + base)     = l0;
    *(__nv_bfloat162*)(sl + base + 2) = l1;
}

__global__ void __launch_bounds__(256) gemm_k(GArgs g) {
    int p = blockIdx.z;
    int e = p / 24, r = p % 24, b = r / 3, s = r % 3;
    if (g_gates[b * 4 + e] == 0.f) return;
    int M = g.m_is_L ? c_L[s] : c_SQ[s];
    int m0 = blockIdx.x * 64;
    if (m0 >= M) return;
    int n0 = blockIdx.y * 128;

    const float* A = bufptr(g.a_id) + (long)p * bufstride(g.a_id);
    const __nv_bfloat16* Wh = g_wh + g.wh_off + (long)(e * 2 + g.layer) * g.w_stride;
    const __nv_bfloat16* Wl = g_wl + g.wh_off + (long)(e * 2 + g.layer) * g.w_stride;
    const float* bias = g.bias + (long)(e * 2 + g.layer) * g.bias_stride;
    float* C = bufptr(g.c_id) + (long)p * bufstride(g.c_id);

    extern __shared__ char dsm[];
    uint32_t smem_u = (uint32_t)__cvta_generic_to_shared(dsm);

    int tid = threadIdx.x;
    // loaders
    int arow = tid >> 2, akq = (tid & 3) << 3;        // A: 64 rows x 4 k-chunks of 8
    int wrow = tid >> 1, wkq = (tid & 1) << 4;        // W: 128 rows x 2 k-chunks of 16
    bool aval = (m0 + arow) < M;
    const float* aptr = A + (long)(m0 + arow) * g.K + akq;
    const __nv_bfloat16* whp = Wh + (long)(n0 + wrow) * g.K + wkq;
    const __nv_bfloat16* wlp = Wl + (long)(n0 + wrow) * g.K + wkq;

    // compute mapping: 8 warps, wm in {0,1}, wn in {0..3}; warp tile 32x32
    int lane = tid & 31, w = tid >> 5;
    int gq_ = lane >> 2, qq = lane & 3;
    int wm = w & 1, wn = w >> 1;
    int abase = wm * 32, wbase = wn * 32;

    // ldmatrix per-lane addressing
    int lr = lane & 7, tq = lane >> 3;
    int a_r = abase + ((tq & 1) << 3) + lr;   // + mf*16
    int a_k = (tq >> 1) << 3;                 // + ks
    int b_r = wbase + ((tq >> 1) << 3) + lr;  // + nfp*16
    int b_k = (tq & 1) << 3;                  // + ks

    float acc[2][4][4];
    #pragma unroll
    for (int i = 0; i < 2; i++)
        #pragma unroll
        for (int j = 0; j < 4; j++)
            #pragma unroll
            for (int k = 0; k < 4; k++) acc[i][j][k] = 0.f;

    int nc = g.K >> 5;
    float4 fa0, fa1;
    uint4 vh0, vh1, vl0, vl1;

    // prefetch chunk 0
    fa0 = fa1 = make_float4(0.f, 0.f, 0.f, 0.f);
    if (aval) { fa0 = *(const float4*)(aptr); fa1 = *(const float4*)(aptr + 4); }
    vh0 = *(const uint4*)(whp);  vh1 = *(const uint4*)(whp + 8);
    vl0 = *(const uint4*)(wlp);  vl1 = *(const uint4*)(wlp + 8);
    {
        __nv_bfloat16* sAh = (__nv_bfloat16*)(dsm);
        __nv_bfloat16* sAl = (__nv_bfloat16*)(dsm + 5120);
        __nv_bfloat16* sWh = (__nv_bfloat16*)(dsm + 10240);
        __nv_bfloat16* sWl = (__nv_bfloat16*)(dsm + 20480);
        pack_store(sAh, sAl, arow * SPITCH + akq, fa0);
        pack_store(sAh, sAl, arow * SPITCH + akq + 4, fa1);
        *(uint4*)&sWh[wrow * SPITCH + wkq]     = vh0;
        *(uint4*)&sWh[wrow * SPITCH + wkq + 8] = vh1;
        *(uint4*)&sWl[wrow * SPITCH + wkq]     = vl0;
        *(uint4*)&sWl[wrow * SPITCH + wkq + 8] = vl1;
    }
    __syncthreads();

    for (int c = 0; c < nc; c++) {
        int st = c & 1;
        bool nx = (c + 1 < nc);
        if (nx) {
            long off = (long)(c + 1) << 5;
            fa0 = fa1 = make_float4(0.f, 0.f, 0.f, 0.f);
            if (aval) { fa0 = *(const float4*)(aptr + off); fa1 = *(const float4*)(aptr + off + 4); }
            vh0 = *(const uint4*)(whp + off);  vh1 = *(const uint4*)(whp + off + 8);
            vl0 = *(const uint4*)(wlp + off);  vl1 = *(const uint4*)(wlp + off + 8);
        }

        uint32_t aH = smem_u + st * STG_BYTES;
        uint32_t aL = aH + 5120;
        uint32_t wH = aH + 10240;
        uint32_t wL = aH + 20480;

        #pragma unroll
        for (int ks = 0; ks < 32; ks += 16) {
            uint32_t Ah[2][4], Al[2][4], Bh[4][2], Bl[4][2];
            #pragma unroll
            for (int mf = 0; mf < 2; mf++) {
                uint32_t off = ((a_r + mf * 16) * SPITCH + a_k + ks) * 2;
                ldsm4(Ah[mf][0], Ah[mf][1], Ah[mf][2], Ah[mf][3], aH + off);
                ldsm4(Al[mf][0], Al[mf][1], Al[mf][2], Al[mf][3], aL + off);
            }
            #pragma unroll
            for (int nfp = 0; nfp < 2; nfp++) {
                uint32_t off = ((b_r + nfp * 16) * SPITCH + b_k + ks) * 2;
                ldsm4(Bh[nfp*2][0], Bh[nfp*2][1], Bh[nfp*2+1][0], Bh[nfp*2+1][1], wH + off);
                ldsm4(Bl[nfp*2][0], Bl[nfp*2][1], Bl[nfp*2+1][0], Bl[nfp*2+1][1], wL + off);
            }
            #pragma unroll
            for (int mf = 0; mf < 2; mf++)
                #pragma unroll
                for (int nf = 0; nf < 4; nf++) {
                    mma_bf16(acc[mf][nf], Ah[mf], Bh[nf]);
                    mma_bf16(acc[mf][nf], Ah[mf], Bl[nf]);
                    mma_bf16(acc[mf][nf], Al[mf], Bh[nf]);
                }
        }

        if (nx) {
            char* base = dsm + (st ^ 1) * STG_BYTES;
            __nv_bfloat16* sAh = (__nv_bfloat16*)(base);
            __nv_bfloat16* sAl = (__nv_bfloat16*)(base + 5120);
            __nv_bfloat16* sWh = (__nv_bfloat16*)(base + 10240);
            __nv_bfloat16* sWl = (__nv_bfloat16*)(base + 20480);
            pack_store(sAh, sAl, arow * SPITCH + akq, fa0);
            pack_store(sAh, sAl, arow * SPITCH + akq + 4, fa1);
            *(uint4*)&sWh[wrow * SPITCH + wkq]     = vh0;
            *(uint4*)&sWh[wrow * SPITCH + wkq + 8] = vh1;
            *(uint4*)&sWl[wrow * SPITCH + wkq]     = vl0;
            *(uint4*)&sWl[wrow * SPITCH + wkq + 8] = vl1;
        }
        __syncthreads();
    }

    const float* lsp = (g.epi == 2) ? (g.ls + (long)(e * 2 + g.layer) * H_) : nullptr;
    #pragma unroll
    for (int mf = 0; mf < 2; mf++) {
        #pragma unroll
        for (int half = 0; half < 2; half++) {
            int m = m0 + abase + mf * 16 + gq_ + half * 8;
            if (m >= M) continue;
            #pragma unroll
            for (int nf = 0; nf < 4; nf++) {
                int n = n0 + wbase + nf * 8 + qq * 2;
                float v0 = acc[mf][nf][half * 2 + 0] + bias[n];
                float v1 = acc[mf][nf][half * 2 + 1] + bias[n + 1];
                long idx = (long)m * g.N + n;
                if (g.epi == 0) {
                    C[idx] = v0; C[idx + 1] = v1;
                } else if (g.epi == 1) {
                    C[idx]     = v0 * 0.5f * (1.f + erff(v0 * 0.70710678118654752f));
                    C[idx + 1] = v1 * 0.5f * (1.f + erff(v1 * 0.70710678118654752f));
                } else {
                    C[idx]     += lsp[n] * v0;
                    C[idx + 1] += lsp[n + 1] * v1;
                }
            }
        }
    }
}

// ---------------- attention (per problem, head, q-row) -----------------------
__global__ void attn_kernel() {
    int p = blockIdx.z;
    int e = p / 24, r = p % 24, b = r / 3, s = r % 3;
    if (g_gates[b * 4 + e] == 0.f) return;
    int sq = c_SQ[s];
    int row = blockIdx.x;
    if (row >= sq) return;
    int L = c_L[s];
    int h = blockIdx.y;
    int t = threadIdx.x;

    __shared__ float sc[320];
    __shared__ float qv[64];
    __shared__ float red[32];
    __shared__ float cbuf[4][64];

    const float* Q = g_q + (long)p * 64 * H_ + (long)row * H_ + h * 64;
    const float* K = g_k + (long)p * 320 * H_ + h * 64;
    const float* V = g_v + (long)p * 320 * H_ + h * 64;

    if (t < 64) qv[t] = Q[t];
    __syncthreads();

    for (int k = t; k < L; k += 256) {
        const float* kr = K + (long)k * H_;
        float d = 0.f;
        #pragma unroll
        for (int dd = 0; dd < 64; dd++) d += qv[dd] * kr[dd];
        sc[k] = d * 0.125f;
    }
    __syncthreads();

    float mx = -1e30f;
    for (int k = t; k < L; k += 256) mx = fmaxf(mx, sc[k]);
    mx = blockReduceMax(mx, red);
    float sum = 0.f;
    for (int k = t; k < L; k += 256) { float ev = expf(sc[k] - mx); sc[k] = ev; sum += ev; }
    sum = blockReduceSum(sum, red);
    float inv = 1.f / sum;

    int d = t & 63, ch = t >> 6;
    float acc = 0.f;
    for (int k = ch; k < L; k += 4) acc += sc[k] * V[(long)k * H_ + d];
    cbuf[ch][d] = acc;
    __syncthreads();
    if (t < 64) {
        float o = (cbuf[0][t] + cbuf[1][t] + cbuf[2][t] + cbuf[3][t]) * inv;
        g_xn[(long)p * 64 * H_ + (long)row * H_ + h * 64 + t] = o;
    }
}

// ---------------- expert-weighted output projection (tensor core, R4 path) ---
#define OSPITCH 40
__global__ void __launch_bounds__(128) out_gemm(const float* __restrict__ outp_b) {
    int b = blockIdx.z;
    int m0 = blockIdx.x * 64;
    int n0 = blockIdx.y * 64;

    __shared__ __nv_bfloat16 sAh[64 * OSPITCH], sAl[64 * OSPITCH];
    __shared__ __nv_bfloat16 sWh[64 * OSPITCH], sWl[64 * OSPITCH];

    int tid = threadIdx.x;
    int lrow = tid >> 1, lkb = (tid & 1) << 4;
    int lane = tid & 31, w = tid >> 5;
    int gq_ = lane >> 2, qq = lane & 3;
    int wm = w >> 1, wn = w & 1;
    int abase = wm * 32, wbase = wn * 32;

    int qg = m0 + lrow;
    bool aval = qg < NQ_;
    int s = 0, lr = 0;
    if (aval) {
        s = (qg < 64) ? 0 : ((qg < 112) ? 1 : 2);
        lr = qg - c_QO[s];
    }

    float tot[2][4][4];
    #pragma unroll
    for (int i = 0; i < 2; i++)
        #pragma unroll
        for (int j = 0; j < 4; j++)
            #pragma unroll
            for (int k = 0; k < 4; k++) tot[i][j][k] = 0.f;

    for (int e = 0; e < 4; e++) {
        float gt = g_gates[b * 4 + e];
        if (gt == 0.f) continue;
        const float* aptr = g_x + ((long)(e * 24 + b * 3 + s) * 64 + lr) * H_ + lkb;
        long wb_off = OFF_OUTP + (long)e * OUT_ * H_ + (long)(n0 + lrow) * H_ + lkb;
        const __nv_bfloat16* whp = g_wh + wb_off;
        const __nv_bfloat16* wlp = g_wl + wb_off;

        float acc[2][4][4];
        #pragma unroll
        for (int i = 0; i < 2; i++)
            #pragma unroll
            for (int j = 0; j < 4; j++)
                #pragma unroll
                for (int k = 0; k < 4; k++) acc[i][j][k] = 0.f;

        float4 fa0, fa1, fa2, fa3;
        uint4 vh0, vh1, vl0, vl1;
        fa0 = fa1 = fa2 = fa3 = make_float4(0.f, 0.f, 0.f, 0.f);
        if (aval) {
            fa0 = *(const float4*)(aptr);      fa1 = *(const float4*)(aptr + 4);
            fa2 = *(const float4*)(aptr + 8);  fa3 = *(const float4*)(aptr + 12);
        }
        vh0 = *(const uint4*)(whp);  vh1 = *(const uint4*)(whp + 8);
        vl0 = *(const uint4*)(wlp);  vl1 = *(const uint4*)(wlp + 8);

        const int nc = H_ >> 5;
        for (int c = 0; c < nc; c++) {
            int sb = lrow * OSPITCH + lkb;
            __syncthreads();
            pack_store(sAh, sAl, sb,      fa0);
            pack_store(sAh, sAl, sb + 4,  fa1);
            pack_store(sAh, sAl, sb + 8,  fa2);
            pack_store(sAh, sAl, sb + 12, fa3);
            *(uint4*)&sWh[sb]     = vh0;  *(uint4*)&sWh[sb + 8] = vh1;
            *(uint4*)&sWl[sb]     = vl0;  *(uint4*)&sWl[sb + 8] = vl1;
            __syncthreads();

            if (c + 1 < nc) {
                long off = (long)(c + 1) << 5;
                fa0 = fa1 = fa2 = fa3 = make_float4(0.f, 0.f, 0.f, 0.f);
                if (aval) {
                    fa0 = *(const float4*)(aptr + off);      fa1 = *(const float4*)(aptr + off + 4);
                    fa2 = *(const float4*)(aptr + off + 8);  fa3 = *(const float4*)(aptr + off + 12);
                }
                vh0 = *(const uint4*)(whp + off);  vh1 = *(const uint4*)(whp + off + 8);
                vl0 = *(const uint4*)(wlp + off);  vl1 = *(const uint4*)(wlp + off + 8);
            }

            #pragma unroll
            for (int ks = 0; ks < 32; ks += 16) {
                int cb = ks + qq * 2;
                uint32_t Ah[2][4], Al[2][4], Bh[4][2], Bl[4][2];
                #pragma unroll
                for (int mf = 0; mf < 2; mf++) {
                    int rr = (abase + mf * 16 + gq_) * OSPITCH;
                    Ah[mf][0] = *(const uint32_t*)&sAh[rr + cb];
                    Ah[mf][1] = *(const uint32_t*)&sAh[rr + 8 * OSPITCH + cb];
                    Ah[mf][2] = *(const uint32_t*)&sAh[rr + cb + 8];
                    Ah[mf][3] = *(const uint32_t*)&sAh[rr + 8 * OSPITCH + cb + 8];
                    Al[mf][0] = *(const uint32_t*)&sAl[rr + cb];
                    Al[mf][1] = *(const uint32_t*)&sAl[rr + 8 * OSPITCH + cb];
                    Al[mf][2] = *(const uint32_t*)&sAl[rr + cb + 8];
                    Al[mf][3] = *(const uint32_t*)&sAl[rr + 8 * OSPITCH + cb + 8];
                }
                #pragma unroll
                for (int nf = 0; nf < 4; nf++) {
                    int rr = (wbase + nf * 8 + gq_) * OSPITCH;
                    Bh[nf][0] = *(const uint32_t*)&sWh[rr + cb];
                    Bh[nf][1] = *(const uint32_t*)&sWh[rr + cb + 8];
                    Bl[nf][0] = *(const uint32_t*)&sWl[rr + cb];
                    Bl[nf][1] = *(const uint32_t*)&sWl[rr + cb + 8];
                }
                #pragma unroll
                for (int mf = 0; mf < 2; mf++)
                    #pragma unroll
                    for (int nf = 0; nf < 4; nf++) {
                        mma_bf16(acc[mf][nf], Ah[mf], Bh[nf]);
                        mma_bf16(acc[mf][nf], Ah[mf], Bl[nf]);
                        mma_bf16(acc[mf][nf], Al[mf], Bh[nf]);
                    }
            }
        }

        const float* bias = outp_b + (long)e * OUT_;
        #pragma unroll
        for (int mf = 0; mf < 2; mf++)
            #pragma unroll
            for (int nf = 0; nf < 4; nf++) {
                int n = n0 + wbase + nf * 8 + qq * 2;
                tot[mf][nf][0] += gt * (acc[mf][nf][0] + bias[n]);
                tot[mf][nf][1] += gt * (acc[mf][nf][1] + bias[n + 1]);
                tot[mf][nf][2] += gt * (acc[mf][nf][2] + bias[n]);
                tot[mf][nf][3] += gt * (acc[mf][nf][3] + bias[n + 1]);
            }
    }

    #pragma unroll
    for (int mf = 0; mf < 2; mf++) {
        #pragma unroll
        for (int half = 0; half < 2; half++) {
            int m = m0 + abase + mf * 16 + gq_ + half * 8;
            if (m >= NQ_) continue;
            #pragma unroll
            for (int nf = 0; nf < 4; nf++) {
                int n = n0 + wbase + nf * 8 + qq * 2;
                g_comb[((long)b * NQ_ + m) * OUT_ + n]     = tot[mf][nf][half * 2 + 0];
                g_comb[((long)b * NQ_ + m) * OUT_ + n + 1] = tot[mf][nf][half * 2 + 1];
            }
        }
    }
}

// ---------------- final RMS + scaling ----------------------------------------
__global__ void rms_kernel(const float* __restrict__ final_w,
                           const float* __restrict__ out_gain,
                           float* __restrict__ out) {
    int q = blockIdx.x, b = blockIdx.y;
    int t = threadIdx.x;
    const float* c = g_comb + ((long)b * NQ_ + q) * OUT_;
    float s2 = 0.f;
    for (int o = t; o < OUT_; o += 256) { float v = c[o]; s2 += v * v; }
    __shared__ float red[32];
    s2 = blockReduceSum(s2, red);
    float rs = rsqrtf(s2 / (float)OUT_ + 1e-6f);
    float* orow = out + ((long)b * NQ_ + q) * OUT_;
    for (int o = t; o < OUT_; o += 256) orow[o] = c[o] * rs * final_w[o] * out_gain[o];
}

// ---------------- host driver ------------------------------------------------
extern "C" void kernel_launch(void* const* d_in, const int* in_sizes, int n_in,
                              void* d_out, int out_size) {
    const float* image_embs = (const float*)d_in[0];
    const float* phys       = (const float*)d_in[1];
    const int*   task_ids   = (const int*)d_in[2];
    const int*   elem_ids   = (const int*)d_in[3];
    const float* query      = (const float*)d_in[4];
    const float* ln1_w      = (const float*)d_in[5];
    const float* ln1_b      = (const float*)d_in[6];
    const float* ln1kv_w    = (const float*)d_in[7];
    const float* ln1kv_b    = (const float*)d_in[8];
    const float* attn_in_w  = (const float*)d_in[9];
    const float* attn_in_b  = (const float*)d_in[10];
    const float* attn_out_w = (const float*)d_in[11];
    const float* attn_out_b = (const float*)d_in[12];
    const float* ls1        = (const float*)d_in[13];
    const float* ls2        = (const float*)d_in[14];
    const float* ln2_w      = (const float*)d_in[15];
    const float* ln2_b      = (const float*)d_in[16];
    const float* fc_w       = (const float*)d_in[17];
    const float* fc_b       = (const float*)d_in[18];
    const float* proj_w     = (const float*)d_in[19];
    const float* proj_b     = (const float*)d_in[20];
    const float* outp_w     = (const float*)d_in[21];
    const float* outp_b     = (const float*)d_in[22];
    const float* task_emb   = (const float*)d_in[23];
    const float* elem_emb   = (const float*)d_in[24];
    const float* gate_ln_w  = (const float*)d_in[25];
    const float* gate_ln_b  = (const float*)d_in[26];
    const float* gate_w     = (const float*)d_in[27];
    const float* gate_b     = (const float*)d_in[28];
    const float* output_gain= (const float*)d_in[29];
    const float* final_w    = (const float*)d_in[30];
    (void)in_sizes; (void)n_in; (void)out_size;

    cudaFuncSetAttribute(gemm_k, cudaFuncAttributeMaxDynamicSharedMemorySize, SMEM_TOTAL);

    split_w<<<4096, 256>>>(attn_in_w,  OFF_ATTNIN,  SZ_ATTNIN);
    split_w<<<2048, 256>>>(attn_out_w, OFF_ATTNOUT, SZ_ATTNOUT);
    split_w<<<4096, 256>>>(fc_w,       OFF_FC,      SZ_FC);
    split_w<<<4096, 256>>>(proj_w,     OFF_PROJ,    SZ_PROJ);
    split_w<<<4096, 256>>>(outp_w,     OFF_OUTP,    SZ_OUTP);

    gate_kernel<<<B_, 256>>>(image_embs, task_ids, elem_ids, task_emb, elem_emb,
                             gate_ln_w, gate_ln_b, gate_w, gate_b);
    build_kernel<<<dim3(320, NP_), 256>>>(query, image_embs, phys);

    for (int l = 0; l < 2; l++) {
        ln_rows<<<dim3(320, NP_), 256>>>(2, 3, ln1kv_w, ln1kv_b, 1, l);
        ln_rows<<<dim3(64, NP_), 256>>>(0, 1, ln1_w, ln1_b, 0, l);

        GArgs gq = {};
        gq.a_id = 1; gq.c_id = 4;
        gq.wh_off = OFF_ATTNIN; gq.w_stride = 3072L * 1024;
        gq.bias = attn_in_b; gq.bias_stride = 3072;
        gq.ls = nullptr; gq.N = 1024; gq.K = 1024;
        gq.m_is_L = 0; gq.epi = 0; gq.layer = l;
        gemm_k<<<dim3(1, 8, NP_), 256, SMEM_TOTAL>>>(gq);

        GArgs gk = gq;
        gk.a_id = 3; gk.c_id = 5;
        gk.wh_off = OFF_ATTNIN + 1024L * 1024; gk.bias = attn_in_b + 1024;
        gk.m_is_L = 1;
        gemm_k<<<dim3(5, 8, NP_), 256, SMEM_TOTAL>>>(gk);

        GArgs gv = gk;
        gv.c_id = 6;
        gv.wh_off = OFF_ATTNIN + 2048L * 1024; gv.bias = attn_in_b + 2048;
        gemm_k<<<dim3(5, 8, NP_), 256, SMEM_TOTAL>>>(gv);

        attn_kernel<<<dim3(64, 16, NP_), 256>>>();

        GArgs go = {};
        go.a_id = 1; go.c_id = 0;
        go.wh_off = OFF_ATTNOUT; go.w_stride = 1024L * 1024;
        go.bias = attn_out_b; go.bias_stride = 1024;
        go.ls = ls1; go.N = 1024; go.K = 1024;
        go.m_is_L = 0; go.epi = 2; go.layer = l;
        gemm_k<<<dim3(1, 8, NP_), 256, SMEM_TOTAL>>>(go);

        ln_rows<<<dim3(64, NP_), 256>>>(0, 1, ln2_w, ln2_b, 0, l);

        GArgs gf = {};
        gf.a_id = 1; gf.c_id = 7;
        gf.wh_off = OFF_FC; gf.w_stride = 4096L * 1024;
        gf.bias = fc_b; gf.bias_stride = 4096;
        gf.ls = nullptr; gf.N = 4096; gf.K = 1024;
        gf.m_is_L = 0; gf.epi = 1; gf.layer = l;
        gemm_k<<<dim3(1, 32, NP_), 256, SMEM_TOTAL>>>(gf);

        GArgs gp = {};
        gp.a_id = 7; gp.c_id = 0;
        gp.wh_off = OFF_PROJ; gp.w_stride = 1024L * 4096;
        gp.bias = proj_b; gp.bias_stride = 1024;
        gp.ls = ls2; gp.N = 1024; gp.K = 4096;
        gp.m_is_L = 0; gp.epi = 2; gp.layer = l;
        gemm_k<<<dim3(1, 8, NP_), 256, SMEM_TOTAL>>>(gp);
    }

    out_gemm<<<dim3(3, 64, B_), 128>>>(outp_b);
    rms_kernel<<<dim3(NQ_, B_), 256>>>(final_w, output_gain, (float*)d_out);
}